// round 11
// baseline (speedup 1.0000x reference)
#include <cuda_runtime.h>
#include <cuda_bf16.h>
#include <math.h>
#include <stdint.h>

#define NBV   336
#define NVAR  21
#define TT    512
#define TP    520
#define PNUM  64
#define DM    128
#define SEA   512
#define DIN   256
#define DSS   16
#define LSEQ  64
#define PRED  96
#define EPS_F 1e-5f
#define MROWS (NBV * PNUM)   // 21504
#define WP    20             // smem word pitch for k-chunk staging
#define AHP   68             // h/mk tile pitch (words)
#define PSP   260            // P tile pitch (words)
#define CSP   132            // C tile pitch (floats)
#define NSPL  32             // mlp2 split-K factor

// ---------------- scratch ----------------
__device__ float    g_mean[NBV];
__device__ float    g_std[NBV];
__device__ float    g_h  [MROWS * DM];
__device__ float    g_hb [MROWS * DM];
__device__ float    g_z   [MROWS * DIN];
__device__ float    g_xcc [MROWS * DIN];
__device__ float    g_y   [MROWS * DIN];
__device__ float    g_mo  [MROWS * DM];
__device__ float    g_t2p [NSPL * NBV * 192];

__device__ __forceinline__ float gelu_exact(float x) {
    return 0.5f * x * (1.0f + erff(x * 0.70710678118654752f));
}
__device__ __forceinline__ float silu_f(float x) {
    return x / (1.0f + __expf(-x));
}
__device__ __forceinline__ uint32_t pack_bf(float a, float b) {
    __nv_bfloat162 t = __floats2bfloat162_rn(a, b);
    return *(uint32_t*)&t;
}
__device__ __forceinline__ void mma_bf16(float c[4], const uint32_t a[4], const uint32_t b[2]) {
    asm volatile("mma.sync.aligned.m16n8k16.row.col.f32.bf16.bf16.f32 "
        "{%0,%1,%2,%3},{%4,%5,%6,%7},{%8,%9},{%0,%1,%2,%3};"
        : "+f"(c[0]), "+f"(c[1]), "+f"(c[2]), "+f"(c[3])
        : "r"(a[0]), "r"(a[1]), "r"(a[2]), "r"(a[3]), "r"(b[0]), "r"(b[1]));
}

// ---------- bf16 64x64 tile core (NT), 128 threads, K-step 32 ----------
__device__ __forceinline__ void gemm_bf16_64(
    const float* __restrict__ A, int lda,
    const float* __restrict__ Bn, int ldb, int Nvalid,
    int m0, int K, int Mmax,
    uint32_t As[64][WP], uint32_t Bs[64][WP],
    float acc[2][4][4])
{
    int tid = threadIdx.x;
    int lane = tid & 31, wid = tid >> 5;
    int warpM = wid & 1, warpN = wid >> 1;
    int g = lane >> 2, tg = lane & 3;
    for (int k0 = 0; k0 < K; k0 += 32) {
        #pragma unroll
        for (int u = 0; u < 4; u++) {
            int f = tid * 4 + u, row = f >> 3, q = f & 7;
            float4 v = make_float4(0.f, 0.f, 0.f, 0.f);
            int gr = m0 + row;
            if (gr < Mmax) v = *(const float4*)(A + (size_t)gr * lda + k0 + q * 4);
            *(uint2*)&As[row][q * 2] = make_uint2(pack_bf(v.x, v.y), pack_bf(v.z, v.w));
        }
        #pragma unroll
        for (int u = 0; u < 4; u++) {
            int f = tid * 4 + u, row = f >> 3, q = f & 7;
            float4 v = make_float4(0.f, 0.f, 0.f, 0.f);
            if (row < Nvalid) v = *(const float4*)(Bn + (size_t)row * ldb + k0 + q * 4);
            *(uint2*)&Bs[row][q * 2] = make_uint2(pack_bf(v.x, v.y), pack_bf(v.z, v.w));
        }
        __syncthreads();
        #pragma unroll
        for (int ks = 0; ks < 2; ks++) {
            int kk = ks * 8;
            uint32_t a[2][4], b[4][2];
            #pragma unroll
            for (int mi = 0; mi < 2; mi++) {
                int mr = warpM * 32 + mi * 16;
                a[mi][0] = As[mr + g][kk + tg];
                a[mi][1] = As[mr + g + 8][kk + tg];
                a[mi][2] = As[mr + g][kk + tg + 4];
                a[mi][3] = As[mr + g + 8][kk + tg + 4];
            }
            #pragma unroll
            for (int ni = 0; ni < 4; ni++) {
                int nr = warpN * 32 + ni * 8 + g;
                b[ni][0] = Bs[nr][kk + tg];
                b[ni][1] = Bs[nr][kk + tg + 4];
            }
            #pragma unroll
            for (int mi = 0; mi < 2; mi++)
                #pragma unroll
                for (int ni = 0; ni < 4; ni++)
                    mma_bf16(acc[mi][ni], a[mi], b[ni]);
        }
        __syncthreads();
    }
}

// ---------------- K1: RevIN + mlp1 fused ----------------
__global__ void __launch_bounds__(512) k_revin_mlp1(
        const float* __restrict__ x,
        const float* __restrict__ rw, const float* __restrict__ rb,
        const float* __restrict__ w1, const float* __restrict__ b1) {
    int bv = blockIdx.x;
    int b = bv / NVAR, v = bv % NVAR;
    int t = threadIdx.x;
    __shared__ float xs[TP];
    float val = x[(size_t)(b * TT + t) * NVAR + v];
    __shared__ float s1[16], s2[16];
    float a = val, q = val * val;
    #pragma unroll
    for (int o = 16; o; o >>= 1) {
        a += __shfl_down_sync(0xffffffffu, a, o);
        q += __shfl_down_sync(0xffffffffu, q, o);
    }
    if ((t & 31) == 0) { s1[t >> 5] = a; s2[t >> 5] = q; }
    __syncthreads();
    __shared__ float mb[2];
    if (t < 32) {
        float a2 = (t < 16) ? s1[t] : 0.f;
        float q2 = (t < 16) ? s2[t] : 0.f;
        #pragma unroll
        for (int o = 8; o; o >>= 1) {
            a2 += __shfl_down_sync(0xffffffffu, a2, o);
            q2 += __shfl_down_sync(0xffffffffu, q2, o);
        }
        if (t == 0) {
            float mean = a2 * (1.0f / TT);
            float var  = q2 * (1.0f / TT) - mean * mean;
            float sd   = sqrtf(var + EPS_F);
            mb[0] = mean; mb[1] = sd;
            g_mean[bv] = mean; g_std[bv] = sd;
        }
    }
    __syncthreads();
    float xnv = (val - mb[0]) / mb[1] * rw[v] + rb[v];
    xs[t] = xnv;
    if (t == TT - 1) {
        #pragma unroll
        for (int i = 0; i < 8; i++) xs[TT + i] = xnv;
    }
    __syncthreads();
    int d = t & 127, pg = t >> 7;
    float wr[16];
    #pragma unroll
    for (int s = 0; s < 16; s++) wr[s] = w1[d * 16 + s];
    float bb = b1[d];
    float* hp = g_h + (size_t)bv * PNUM * DM;
    #pragma unroll
    for (int pi = 0; pi < 16; pi++) {
        int p = pg * 16 + pi;
        float acc = bb;
        const float* xp = xs + p * 8;
        #pragma unroll
        for (int s = 0; s < 16; s++) acc = fmaf(xp[s], wr[s], acc);
        hp[p * DM + d] = acc;
    }
}

// ---------------- K2: fused attention, 101KB smem -> 2 CTA/SM ----------------
// smem: Ah[64*AHP] + Bw[64*AHP] + Ps[64*PSP]; Cs aliases Ps.
__global__ void __launch_bounds__(256, 2) k_attn(
        const float* __restrict__ mk, const float* __restrict__ mv,
        const float* __restrict__ lnw, const float* __restrict__ lnb) {
    extern __shared__ uint32_t smw[];
    uint32_t* Ah = smw;                       // [64][AHP]
    uint32_t* Bw = Ah + 64 * AHP;             // [64][AHP] scores-B / [128][WP] av-B
    uint32_t* Ps = Bw + 64 * AHP;             // [64][PSP]
    float*    Cs = (float*)Ps;                // aliases Ps, [64][CSP]
    int tid = threadIdx.x, lane = tid & 31, wid = tid >> 5;
    int warpM = wid & 1, warpN = wid >> 1;    // warpN 0..3
    int g = lane >> 2, tg = lane & 3;
    int m0 = blockIdx.x * 64;

    // stage h (64x128) -> Ah bf16
    #pragma unroll
    for (int u = 0; u < 8; u++) {
        int f = u * 256 + tid;
        int row = f >> 5, q = f & 31;
        float4 v = *(const float4*)(g_h + (size_t)(m0 + row) * DM + q * 4);
        Ah[row * AHP + q * 2]     = pack_bf(v.x, v.y);
        Ah[row * AHP + q * 2 + 1] = pack_bf(v.z, v.w);
    }
    // ---- scores: 8 panels of 64x64 ----
    for (int nc = 0; nc < 8; nc++) {
        __syncthreads();
        #pragma unroll
        for (int u = 0; u < 8; u++) {
            int f = u * 256 + tid;            // 2048 float4 (64 rows x 32)
            int row = f >> 5, q = f & 31;
            float4 v = *(const float4*)(mk + (size_t)(nc * 64 + row) * DM + q * 4);
            Bw[row * AHP + q * 2]     = pack_bf(v.x, v.y);
            Bw[row * AHP + q * 2 + 1] = pack_bf(v.z, v.w);
        }
        __syncthreads();
        float acc[2][2][4];
        #pragma unroll
        for (int i = 0; i < 2; i++)
            #pragma unroll
            for (int j = 0; j < 2; j++)
                #pragma unroll
                for (int c = 0; c < 4; c++) acc[i][j][c] = 0.f;
        #pragma unroll
        for (int ks = 0; ks < 8; ks++) {
            uint32_t a[2][4], b[2][2];
            #pragma unroll
            for (int mi = 0; mi < 2; mi++) {
                int mr = warpM * 32 + mi * 16;
                a[mi][0] = Ah[(mr + g) * AHP + ks * 8 + tg];
                a[mi][1] = Ah[(mr + g + 8) * AHP + ks * 8 + tg];
                a[mi][2] = Ah[(mr + g) * AHP + ks * 8 + tg + 4];
                a[mi][3] = Ah[(mr + g + 8) * AHP + ks * 8 + tg + 4];
            }
            #pragma unroll
            for (int ni = 0; ni < 2; ni++) {
                int nr = warpN * 16 + ni * 8 + g;
                b[ni][0] = Bw[nr * AHP + ks * 8 + tg];
                b[ni][1] = Bw[nr * AHP + ks * 8 + tg + 4];
            }
            #pragma unroll
            for (int mi = 0; mi < 2; mi++)
                #pragma unroll
                for (int ni = 0; ni < 2; ni++)
                    mma_bf16(acc[mi][ni], a[mi], b[ni]);
        }
        #pragma unroll
        for (int mi = 0; mi < 2; mi++)
            #pragma unroll
            for (int ni = 0; ni < 2; ni++) {
                int row = warpM * 32 + mi * 16 + g;
                int wcol = nc * 32 + warpN * 8 + ni * 4 + tg;
                Ps[row * PSP + wcol]       = pack_bf(acc[mi][ni][0], acc[mi][ni][1]);
                Ps[(row + 8) * PSP + wcol] = pack_bf(acc[mi][ni][2], acc[mi][ni][3]);
            }
    }
    __syncthreads();
    // ---- softmax in place (warp per row, 8 rows per warp) ----
    for (int rr = 0; rr < 8; rr++) {
        int row = wid * 8 + rr;
        uint32_t w8[8];
        *(uint4*)&w8[0] = *(uint4*)&Ps[row * PSP + lane * 8];
        *(uint4*)&w8[4] = *(uint4*)&Ps[row * PSP + lane * 8 + 4];
        float vals[16];
        #pragma unroll
        for (int k = 0; k < 8; k++) {
            float2 f = __bfloat1622float2(*(__nv_bfloat162*)&w8[k]);
            vals[k * 2] = f.x; vals[k * 2 + 1] = f.y;
        }
        float mx = -1e30f;
        #pragma unroll
        for (int i = 0; i < 16; i++) mx = fmaxf(mx, vals[i]);
        #pragma unroll
        for (int o = 16; o; o >>= 1) mx = fmaxf(mx, __shfl_xor_sync(0xffffffffu, mx, o));
        float sum = 0.f;
        #pragma unroll
        for (int i = 0; i < 16; i++) { vals[i] = __expf(vals[i] - mx); sum += vals[i]; }
        #pragma unroll
        for (int o = 16; o; o >>= 1) sum += __shfl_xor_sync(0xffffffffu, sum, o);
        float inv = 1.0f / sum;
        #pragma unroll
        for (int k = 0; k < 8; k++)
            w8[k] = pack_bf(vals[k * 2] * inv, vals[k * 2 + 1] * inv);
        *(uint4*)&Ps[row * PSP + lane * 8]     = *(uint4*)&w8[0];
        *(uint4*)&Ps[row * PSP + lane * 8 + 4] = *(uint4*)&w8[4];
    }
    // ---- AV: P(64x512) @ mv^T(128x512) ----
    float acc[2][4][4];
    #pragma unroll
    for (int i = 0; i < 2; i++)
        #pragma unroll
        for (int j = 0; j < 4; j++)
            #pragma unroll
            for (int c = 0; c < 4; c++) acc[i][j][c] = 0.f;
    for (int k0 = 0; k0 < SEA; k0 += 32) {
        __syncthreads();
        #pragma unroll
        for (int u = 0; u < 4; u++) {
            int f = tid * 4 + u, row = f >> 3, q = f & 7;
            float4 v = *(const float4*)(mv + (size_t)row * SEA + k0 + q * 4);
            *(uint2*)&Bw[row * WP + q * 2] = make_uint2(pack_bf(v.x, v.y), pack_bf(v.z, v.w));
        }
        __syncthreads();
        #pragma unroll
        for (int ks = 0; ks < 2; ks++) {
            int kk = ks * 8;
            uint32_t a[2][4], b[4][2];
            #pragma unroll
            for (int mi = 0; mi < 2; mi++) {
                int mr = warpM * 32 + mi * 16;
                a[mi][0] = Ps[(mr + g) * PSP + (k0 >> 1) + kk + tg];
                a[mi][1] = Ps[(mr + g + 8) * PSP + (k0 >> 1) + kk + tg];
                a[mi][2] = Ps[(mr + g) * PSP + (k0 >> 1) + kk + tg + 4];
                a[mi][3] = Ps[(mr + g + 8) * PSP + (k0 >> 1) + kk + tg + 4];
            }
            #pragma unroll
            for (int ni = 0; ni < 4; ni++) {
                int nr = warpN * 32 + ni * 8 + g;
                b[ni][0] = Bw[nr * WP + kk + tg];
                b[ni][1] = Bw[nr * WP + kk + tg + 4];
            }
            #pragma unroll
            for (int mi = 0; mi < 2; mi++)
                #pragma unroll
                for (int ni = 0; ni < 4; ni++)
                    mma_bf16(acc[mi][ni], a[mi], b[ni]);
        }
    }
    __syncthreads();   // all reads of Ps done; Cs may now overwrite it
    #pragma unroll
    for (int mi = 0; mi < 2; mi++)
        #pragma unroll
        for (int ni = 0; ni < 4; ni++) {
            int row = warpM * 32 + mi * 16 + g;
            int col = warpN * 32 + ni * 8 + tg * 2;
            *(float2*)&Cs[row * CSP + col]       = make_float2(acc[mi][ni][0], acc[mi][ni][1]);
            *(float2*)&Cs[(row + 8) * CSP + col] = make_float2(acc[mi][ni][2], acc[mi][ni][3]);
        }
    __syncthreads();
    for (int it = 0; it < 8; it++) {
        int r = wid * 8 + it;
        int gr = m0 + r;
        float vv[4], s = 0.f, q = 0.f;
        #pragma unroll
        for (int qq = 0; qq < 4; qq++) {
            vv[qq] = Cs[r * CSP + lane + qq * 32];
            s += vv[qq]; q += vv[qq] * vv[qq];
        }
        #pragma unroll
        for (int o = 16; o; o >>= 1) {
            s += __shfl_xor_sync(0xffffffffu, s, o);
            q += __shfl_xor_sync(0xffffffffu, q, o);
        }
        float mu = s * (1.0f / DM);
        float var = q * (1.0f / DM) - mu * mu;
        float istd = rsqrtf(var + EPS_F);
        #pragma unroll
        for (int qq = 0; qq < 4; qq++) {
            int d = lane + qq * 32;
            float ln = (vv[qq] - mu) * istd * lnw[d] + lnb[d];
            g_hb[(size_t)gr * DM + d] = gelu_exact(ln) + g_h[(size_t)gr * DM + d];
        }
    }
}

// ---------------- K3: in_proj + fused depthwise conv + SiLU ----------------
__global__ void __launch_bounds__(128) k_inproj(const float* __restrict__ W,
                        const float* __restrict__ cw, const float* __restrict__ cbv) {
    __shared__ uint32_t As[64][WP], Bs[64][WP];
    __shared__ float Cs[64][68];
    float acc[2][4][4];
    #pragma unroll
    for (int i = 0; i < 2; i++)
        #pragma unroll
        for (int j = 0; j < 4; j++)
            #pragma unroll
            for (int c = 0; c < 4; c++) acc[i][j][c] = 0.f;
    int m0 = blockIdx.x * 64, n0 = blockIdx.y * 64;
    gemm_bf16_64(g_hb, DM, W + (size_t)n0 * DM, DM, 64, m0, DM, 1 << 30, As, Bs, acc);
    int tid = threadIdx.x;
    int lane = tid & 31, wid = tid >> 5;
    int warpM = wid & 1, warpN = wid >> 1;
    int g = lane >> 2, tg = lane & 3;
    if (n0 >= 256) {
        int cb = n0 - 256;
        #pragma unroll
        for (int mi = 0; mi < 2; mi++)
            #pragma unroll
            for (int ni = 0; ni < 4; ni++) {
                int row = m0 + warpM * 32 + mi * 16 + g;
                int col = cb + warpN * 32 + ni * 8 + tg * 2;
                *(float2*)&g_z[(size_t)row * DIN + col] = make_float2(acc[mi][ni][0], acc[mi][ni][1]);
                *(float2*)&g_z[(size_t)(row + 8) * DIN + col] = make_float2(acc[mi][ni][2], acc[mi][ni][3]);
            }
        return;
    }
    #pragma unroll
    for (int mi = 0; mi < 2; mi++)
        #pragma unroll
        for (int ni = 0; ni < 4; ni++) {
            int row = warpM * 32 + mi * 16 + g;
            int col = warpN * 32 + ni * 8 + tg * 2;
            *(float2*)&Cs[row][col] = make_float2(acc[mi][ni][0], acc[mi][ni][1]);
            *(float2*)&Cs[row + 8][col] = make_float2(acc[mi][ni][2], acc[mi][ni][3]);
        }
    __syncthreads();
    int cb = n0;
    for (int idx = tid; idx < 64 * 64; idx += 128) {
        int l = idx >> 6, c = idx & 63;
        int gc = cb + c;
        float x0 = (l >= 3) ? Cs[l - 3][c] : 0.f;
        float x1 = (l >= 2) ? Cs[l - 2][c] : 0.f;
        float x2 = (l >= 1) ? Cs[l - 1][c] : 0.f;
        float x3 = Cs[l][c];
        const float4 wv = *(const float4*)(cw + gc * 4);
        float t = fmaf(x0, wv.x, fmaf(x1, wv.y, fmaf(x2, wv.z, fmaf(x3, wv.w, cbv[gc]))));
        g_xcc[(size_t)(m0 + l) * DIN + gc] = silu_f(t);
    }
}

// ---------------- K4: x_proj + dt_proj + softplus + scan (all fused) --------
__global__ void k_scan(const float* __restrict__ A_log, const float* __restrict__ D_ssm,
                       const float* __restrict__ dtw, const float* __restrict__ dtb,
                       const float* __restrict__ xpw) {
    int bv = blockIdx.x, tid = threadIdx.x;   // 256
    __shared__ float xs[8 * DIN];
    __shared__ float dbl[LSEQ][40];
    const float* xcc = g_xcc + (size_t)bv * LSEQ * DIN;
    // x_proj: 64 tokens x 40 outputs, K=256
    for (int lt = 0; lt < 8; lt++) {
        for (int i = tid; i < 8 * DIN; i += 256) xs[i] = xcc[lt * 8 * DIN + i];
        __syncthreads();
        int w = tid >> 5, lane = tid & 31;
        const float4* x4 = (const float4*)(xs + w * DIN);
        for (int o = lane; o < 40; o += 32) {
            const float4* wp = (const float4*)(xpw + o * DIN);
            float acc = 0.f;
            #pragma unroll 8
            for (int k = 0; k < 64; k++) {
                float4 aq = x4[k]; float4 bq = wp[k];
                acc = fmaf(aq.x, bq.x, acc);
                acc = fmaf(aq.y, bq.y, acc);
                acc = fmaf(aq.z, bq.z, acc);
                acc = fmaf(aq.w, bq.w, acc);
            }
            dbl[lt * 8 + w][o] = acc;
        }
        __syncthreads();
    }
    // scan
    int c = tid;
    float dw[8];
    #pragma unroll
    for (int r = 0; r < 8; r++) dw[r] = dtw[c * 8 + r];
    float db = dtb[c];
    float As[DSS];
    #pragma unroll
    for (int s = 0; s < DSS; s++) As[s] = -expf(A_log[c * DSS + s]);
    float Dv = D_ssm[c];
    float st[DSS];
    #pragma unroll
    for (int s = 0; s < DSS; s++) st[s] = 0.f;
    size_t base = (size_t)bv * LSEQ * DIN;
    for (int l = 0; l < LSEQ; l++) {
        float dt = db;
        #pragma unroll
        for (int r = 0; r < 8; r++) dt = fmaf(dbl[l][r], dw[r], dt);
        float d = (dt > 20.f) ? dt : log1pf(expf(dt));
        float u  = g_xcc[base + l * DIN + c];
        float zv = g_z  [base + l * DIN + c];
        float du = d * u;
        float y = 0.f;
        #pragma unroll
        for (int s = 0; s < DSS; s++) {
            float dA = __expf(d * As[s]);
            st[s] = fmaf(st[s], dA, du * dbl[l][8 + s]);
            y = fmaf(st[s], dbl[l][24 + s], y);
        }
        y = fmaf(Dv, u, y);
        y *= silu_f(zv);
        g_y[base + l * DIN + c] = y;
    }
}

// ---------------- K5: out_proj (21504x128x256) ----------------
__global__ void __launch_bounds__(128) k_outproj(const float* __restrict__ W) {
    __shared__ uint32_t As[64][WP], Bs[64][WP];
    float acc[2][4][4];
    #pragma unroll
    for (int i = 0; i < 2; i++)
        #pragma unroll
        for (int j = 0; j < 4; j++)
            #pragma unroll
            for (int c = 0; c < 4; c++) acc[i][j][c] = 0.f;
    int m0 = blockIdx.x * 64, n0 = blockIdx.y * 64;
    gemm_bf16_64(g_y, DIN, W + (size_t)n0 * DIN, DIN, 64, m0, DIN, 1 << 30, As, Bs, acc);
    int lane = threadIdx.x & 31, wid = threadIdx.x >> 5;
    int warpM = wid & 1, warpN = wid >> 1;
    int g = lane >> 2, tg = lane & 3;
    #pragma unroll
    for (int mi = 0; mi < 2; mi++)
        #pragma unroll
        for (int ni = 0; ni < 4; ni++) {
            int row = m0 + warpM * 32 + mi * 16 + g;
            int col = n0 + warpN * 32 + ni * 8 + tg * 2;
            *(float2*)&g_mo[(size_t)row * DM + col] = make_float2(acc[mi][ni][0], acc[mi][ni][1]);
            *(float2*)&g_mo[(size_t)(row + 8) * DM + col] = make_float2(acc[mi][ni][2], acc[mi][ni][3]);
        }
}

// ---------------- K6: mlp2 split-K partials (32 splits of K=256) -----------
__global__ void __launch_bounds__(128) k_mlp2p(const float* __restrict__ W) {
    __shared__ uint32_t As[64][WP], Bs[64][WP];
    float acc[2][4][4];
    #pragma unroll
    for (int i = 0; i < 2; i++)
        #pragma unroll
        for (int j = 0; j < 4; j++)
            #pragma unroll
            for (int c = 0; c < 4; c++) acc[i][j][c] = 0.f;
    int m0 = blockIdx.x * 64, n0 = blockIdx.y * 64, s = blockIdx.z;
    const float* A = g_mo + (size_t)s * 256;
    const float* B = W + (size_t)n0 * 8192 + (size_t)s * 256;
    gemm_bf16_64(A, 8192, B, 8192, 64, m0, 256, NBV, As, Bs, acc);
    int lane = threadIdx.x & 31, wid = threadIdx.x >> 5;
    int warpM = wid & 1, warpN = wid >> 1;
    int g = lane >> 2, tg = lane & 3;
    #pragma unroll
    for (int mi = 0; mi < 2; mi++)
        #pragma unroll
        for (int ni = 0; ni < 4; ni++) {
            int row = m0 + warpM * 32 + mi * 16 + g;
            int col = n0 + warpN * 32 + ni * 8 + tg * 2;
            if (row < NBV)
                *(float2*)&g_t2p[((size_t)s * NBV + row) * 192 + col] =
                    make_float2(acc[mi][ni][0], acc[mi][ni][1]);
            if (row + 8 < NBV)
                *(float2*)&g_t2p[((size_t)s * NBV + row + 8) * 192 + col] =
                    make_float2(acc[mi][ni][2], acc[mi][ni][3]);
        }
}

// ---------------- K7: reduce + GELU + mlp3 + denorm ----------------
__global__ void k_mlp2fin3(const float* __restrict__ bias2,
                           const float* __restrict__ W3, const float* __restrict__ b3,
                           const float* __restrict__ rw, const float* __restrict__ rb,
                           float* __restrict__ out) {
    int bv = blockIdx.x;
    int b = bv / NVAR, v = bv % NVAR;
    int tid = threadIdx.x;   // 192
    __shared__ float ts[192];
    float sum = 0.f;
    #pragma unroll
    for (int s = 0; s < NSPL; s++) sum += g_t2p[((size_t)s * NBV + bv) * 192 + tid];
    ts[tid] = gelu_exact(sum + bias2[tid]);
    __syncthreads();
    if (tid < PRED) {
        float acc = b3[tid];
        const float* w = W3 + tid * 192;
        #pragma unroll 4
        for (int j = 0; j < 192; j++) acc = fmaf(ts[j], w[j], acc);
        float val = (acc - rb[v]) / (rw[v] + 1e-10f) * g_std[bv] + g_mean[bv];
        out[((size_t)b * PRED + tid) * NVAR + v] = val;
    }
}

// ---------------- launch ----------------
extern "C" void kernel_launch(void* const* d_in, const int* in_sizes, int n_in,
                              void* d_out, int out_size) {
    const float* x         = (const float*)d_in[0];
    const float* revin_w   = (const float*)d_in[1];
    const float* revin_b   = (const float*)d_in[2];
    const float* mlp1_w    = (const float*)d_in[3];
    const float* mlp1_b    = (const float*)d_in[4];
    const float* mk_w      = (const float*)d_in[5];
    const float* mv_w      = (const float*)d_in[6];
    const float* ln_w      = (const float*)d_in[7];
    const float* ln_b      = (const float*)d_in[8];
    const float* in_proj_w = (const float*)d_in[9];
    const float* conv_w    = (const float*)d_in[10];
    const float* conv_b    = (const float*)d_in[11];
    const float* x_proj_w  = (const float*)d_in[12];
    const float* dt_proj_w = (const float*)d_in[13];
    const float* dt_proj_b = (const float*)d_in[14];
    const float* A_log     = (const float*)d_in[15];
    const float* D_ssm     = (const float*)d_in[16];
    const float* out_proj_w= (const float*)d_in[17];
    const float* mlp2_w    = (const float*)d_in[18];
    const float* mlp2_b    = (const float*)d_in[19];
    const float* mlp3_w    = (const float*)d_in[20];
    const float* mlp3_b    = (const float*)d_in[21];
    float* out = (float*)d_out;

    const int attn_smem = (64 * AHP + 64 * AHP + 64 * PSP) * 4;   // 101376 B
    cudaFuncSetAttribute(k_attn, cudaFuncAttributeMaxDynamicSharedMemorySize, attn_smem);

    k_revin_mlp1<<<NBV, 512>>>(x, revin_w, revin_b, mlp1_w, mlp1_b);
    k_attn    <<<NBV, 256, attn_smem>>>(mk_w, mv_w, ln_w, ln_b);
    k_inproj  <<<dim3(MROWS / 64, 8), 128>>>(in_proj_w, conv_w, conv_b);
    k_scan    <<<NBV, 256>>>(A_log, D_ssm, dt_proj_w, dt_proj_b, x_proj_w);
    k_outproj <<<dim3(MROWS / 64, 2), 128>>>(out_proj_w);
    k_mlp2p   <<<dim3(6, 3, NSPL), 128>>>(mlp2_w);
    k_mlp2fin3<<<NBV, 192>>>(mlp2_b, mlp3_w, mlp3_b, revin_w, revin_b, out);
}

// round 13
// speedup vs baseline: 1.8344x; 1.8344x over previous
#include <cuda_runtime.h>
#include <cuda_bf16.h>
#include <math.h>
#include <stdint.h>

#define NBV   336
#define NVAR  21
#define TT    512
#define TP    520
#define PNUM  64
#define DM    128
#define SEA   512
#define DIN   256
#define DSS   16
#define LSEQ  64
#define PRED  96
#define EPS_F 1e-5f
#define MROWS (NBV * PNUM)   // 21504
#define WP    20             // smem word pitch for k-chunk staging
#define AHP   68             // h/mk tile pitch (words)
#define PSP   260            // P tile pitch (words)
#define CSP   132            // C tile pitch (floats)
#define NSPL  32             // mlp2 split-K factor

// ---------------- scratch ----------------
__device__ float    g_mean[NBV];
__device__ float    g_std[NBV];
__device__ float    g_h  [MROWS * DM];
__device__ float    g_hb [MROWS * DM];
__device__ float    g_z   [MROWS * DIN];
__device__ float    g_xcc [MROWS * DIN];
__device__ float    g_dbl [MROWS * 40];
__device__ float    g_y   [MROWS * DIN];
__device__ float    g_mo  [MROWS * DM];
__device__ float    g_t2p [NSPL * NBV * 192];

__device__ __forceinline__ float gelu_exact(float x) {
    return 0.5f * x * (1.0f + erff(x * 0.70710678118654752f));
}
__device__ __forceinline__ float silu_f(float x) {
    return x / (1.0f + __expf(-x));
}
__device__ __forceinline__ uint32_t pack_bf(float a, float b) {
    __nv_bfloat162 t = __floats2bfloat162_rn(a, b);
    return *(uint32_t*)&t;
}
__device__ __forceinline__ void mma_bf16(float c[4], const uint32_t a[4], const uint32_t b[2]) {
    asm volatile("mma.sync.aligned.m16n8k16.row.col.f32.bf16.bf16.f32 "
        "{%0,%1,%2,%3},{%4,%5,%6,%7},{%8,%9},{%0,%1,%2,%3};"
        : "+f"(c[0]), "+f"(c[1]), "+f"(c[2]), "+f"(c[3])
        : "r"(a[0]), "r"(a[1]), "r"(a[2]), "r"(a[3]), "r"(b[0]), "r"(b[1]));
}

// ---------- bf16 64x64 tile core (NT), 128 threads, K-step 32 ----------
__device__ __forceinline__ void gemm_bf16_64(
    const float* __restrict__ A, int lda,
    const float* __restrict__ Bn, int ldb, int Nvalid,
    int m0, int K, int Mmax,
    uint32_t As[64][WP], uint32_t Bs[64][WP],
    float acc[2][4][4])
{
    int tid = threadIdx.x;
    int lane = tid & 31, wid = tid >> 5;
    int warpM = wid & 1, warpN = wid >> 1;
    int g = lane >> 2, tg = lane & 3;
    for (int k0 = 0; k0 < K; k0 += 32) {
        #pragma unroll
        for (int u = 0; u < 4; u++) {
            int f = tid * 4 + u, row = f >> 3, q = f & 7;
            float4 v = make_float4(0.f, 0.f, 0.f, 0.f);
            int gr = m0 + row;
            if (gr < Mmax) v = *(const float4*)(A + (size_t)gr * lda + k0 + q * 4);
            *(uint2*)&As[row][q * 2] = make_uint2(pack_bf(v.x, v.y), pack_bf(v.z, v.w));
        }
        #pragma unroll
        for (int u = 0; u < 4; u++) {
            int f = tid * 4 + u, row = f >> 3, q = f & 7;
            float4 v = make_float4(0.f, 0.f, 0.f, 0.f);
            if (row < Nvalid) v = *(const float4*)(Bn + (size_t)row * ldb + k0 + q * 4);
            *(uint2*)&Bs[row][q * 2] = make_uint2(pack_bf(v.x, v.y), pack_bf(v.z, v.w));
        }
        __syncthreads();
        #pragma unroll
        for (int ks = 0; ks < 2; ks++) {
            int kk = ks * 8;
            uint32_t a[2][4], b[4][2];
            #pragma unroll
            for (int mi = 0; mi < 2; mi++) {
                int mr = warpM * 32 + mi * 16;
                a[mi][0] = As[mr + g][kk + tg];
                a[mi][1] = As[mr + g + 8][kk + tg];
                a[mi][2] = As[mr + g][kk + tg + 4];
                a[mi][3] = As[mr + g + 8][kk + tg + 4];
            }
            #pragma unroll
            for (int ni = 0; ni < 4; ni++) {
                int nr = warpN * 32 + ni * 8 + g;
                b[ni][0] = Bs[nr][kk + tg];
                b[ni][1] = Bs[nr][kk + tg + 4];
            }
            #pragma unroll
            for (int mi = 0; mi < 2; mi++)
                #pragma unroll
                for (int ni = 0; ni < 4; ni++)
                    mma_bf16(acc[mi][ni], a[mi], b[ni]);
        }
        __syncthreads();
    }
}

// ---------------- K1: RevIN + mlp1 fused ----------------
__global__ void __launch_bounds__(512) k_revin_mlp1(
        const float* __restrict__ x,
        const float* __restrict__ rw, const float* __restrict__ rb,
        const float* __restrict__ w1, const float* __restrict__ b1) {
    int bv = blockIdx.x;
    int b = bv / NVAR, v = bv % NVAR;
    int t = threadIdx.x;
    __shared__ float xs[TP];
    float val = x[(size_t)(b * TT + t) * NVAR + v];
    __shared__ float s1[16], s2[16];
    float a = val, q = val * val;
    #pragma unroll
    for (int o = 16; o; o >>= 1) {
        a += __shfl_down_sync(0xffffffffu, a, o);
        q += __shfl_down_sync(0xffffffffu, q, o);
    }
    if ((t & 31) == 0) { s1[t >> 5] = a; s2[t >> 5] = q; }
    __syncthreads();
    __shared__ float mb[2];
    if (t < 32) {
        float a2 = (t < 16) ? s1[t] : 0.f;
        float q2 = (t < 16) ? s2[t] : 0.f;
        #pragma unroll
        for (int o = 8; o; o >>= 1) {
            a2 += __shfl_down_sync(0xffffffffu, a2, o);
            q2 += __shfl_down_sync(0xffffffffu, q2, o);
        }
        if (t == 0) {
            float mean = a2 * (1.0f / TT);
            float var  = q2 * (1.0f / TT) - mean * mean;
            float sd   = sqrtf(var + EPS_F);
            mb[0] = mean; mb[1] = sd;
            g_mean[bv] = mean; g_std[bv] = sd;
        }
    }
    __syncthreads();
    float xnv = (val - mb[0]) / mb[1] * rw[v] + rb[v];
    xs[t] = xnv;
    if (t == TT - 1) {
        #pragma unroll
        for (int i = 0; i < 8; i++) xs[TT + i] = xnv;
    }
    __syncthreads();
    int d = t & 127, pg = t >> 7;
    float wr[16];
    #pragma unroll
    for (int s = 0; s < 16; s++) wr[s] = w1[d * 16 + s];
    float bb = b1[d];
    float* hp = g_h + (size_t)bv * PNUM * DM;
    #pragma unroll
    for (int pi = 0; pi < 16; pi++) {
        int p = pg * 16 + pi;
        float acc = bb;
        const float* xp = xs + p * 8;
        #pragma unroll
        for (int s = 0; s < 16; s++) acc = fmaf(xp[s], wr[s], acc);
        hp[p * DM + d] = acc;
    }
}

// ---------------- K2: fused attention, 101KB smem -> 2 CTA/SM ----------------
__global__ void __launch_bounds__(256, 2) k_attn(
        const float* __restrict__ mk, const float* __restrict__ mv,
        const float* __restrict__ lnw, const float* __restrict__ lnb) {
    extern __shared__ uint32_t smw[];
    uint32_t* Ah = smw;                       // [64][AHP]
    uint32_t* Bw = Ah + 64 * AHP;             // [64][AHP] scores-B / [128][WP] av-B
    uint32_t* Ps = Bw + 64 * AHP;             // [64][PSP]
    float*    Cs = (float*)Ps;                // aliases Ps, [64][CSP]
    int tid = threadIdx.x, lane = tid & 31, wid = tid >> 5;
    int warpM = wid & 1, warpN = wid >> 1;
    int g = lane >> 2, tg = lane & 3;
    int m0 = blockIdx.x * 64;

    #pragma unroll
    for (int u = 0; u < 8; u++) {
        int f = u * 256 + tid;
        int row = f >> 5, q = f & 31;
        float4 v = *(const float4*)(g_h + (size_t)(m0 + row) * DM + q * 4);
        Ah[row * AHP + q * 2]     = pack_bf(v.x, v.y);
        Ah[row * AHP + q * 2 + 1] = pack_bf(v.z, v.w);
    }
    for (int nc = 0; nc < 8; nc++) {
        __syncthreads();
        #pragma unroll
        for (int u = 0; u < 8; u++) {
            int f = u * 256 + tid;
            int row = f >> 5, q = f & 31;
            float4 v = *(const float4*)(mk + (size_t)(nc * 64 + row) * DM + q * 4);
            Bw[row * AHP + q * 2]     = pack_bf(v.x, v.y);
            Bw[row * AHP + q * 2 + 1] = pack_bf(v.z, v.w);
        }
        __syncthreads();
        float acc[2][2][4];
        #pragma unroll
        for (int i = 0; i < 2; i++)
            #pragma unroll
            for (int j = 0; j < 2; j++)
                #pragma unroll
                for (int c = 0; c < 4; c++) acc[i][j][c] = 0.f;
        #pragma unroll
        for (int ks = 0; ks < 8; ks++) {
            uint32_t a[2][4], b[2][2];
            #pragma unroll
            for (int mi = 0; mi < 2; mi++) {
                int mr = warpM * 32 + mi * 16;
                a[mi][0] = Ah[(mr + g) * AHP + ks * 8 + tg];
                a[mi][1] = Ah[(mr + g + 8) * AHP + ks * 8 + tg];
                a[mi][2] = Ah[(mr + g) * AHP + ks * 8 + tg + 4];
                a[mi][3] = Ah[(mr + g + 8) * AHP + ks * 8 + tg + 4];
            }
            #pragma unroll
            for (int ni = 0; ni < 2; ni++) {
                int nr = warpN * 16 + ni * 8 + g;
                b[ni][0] = Bw[nr * AHP + ks * 8 + tg];
                b[ni][1] = Bw[nr * AHP + ks * 8 + tg + 4];
            }
            #pragma unroll
            for (int mi = 0; mi < 2; mi++)
                #pragma unroll
                for (int ni = 0; ni < 2; ni++)
                    mma_bf16(acc[mi][ni], a[mi], b[ni]);
        }
        #pragma unroll
        for (int mi = 0; mi < 2; mi++)
            #pragma unroll
            for (int ni = 0; ni < 2; ni++) {
                int row = warpM * 32 + mi * 16 + g;
                int wcol = nc * 32 + warpN * 8 + ni * 4 + tg;
                Ps[row * PSP + wcol]       = pack_bf(acc[mi][ni][0], acc[mi][ni][1]);
                Ps[(row + 8) * PSP + wcol] = pack_bf(acc[mi][ni][2], acc[mi][ni][3]);
            }
    }
    __syncthreads();
    for (int rr = 0; rr < 8; rr++) {
        int row = wid * 8 + rr;
        uint32_t w8[8];
        *(uint4*)&w8[0] = *(uint4*)&Ps[row * PSP + lane * 8];
        *(uint4*)&w8[4] = *(uint4*)&Ps[row * PSP + lane * 8 + 4];
        float vals[16];
        #pragma unroll
        for (int k = 0; k < 8; k++) {
            float2 f = __bfloat1622float2(*(__nv_bfloat162*)&w8[k]);
            vals[k * 2] = f.x; vals[k * 2 + 1] = f.y;
        }
        float mx = -1e30f;
        #pragma unroll
        for (int i = 0; i < 16; i++) mx = fmaxf(mx, vals[i]);
        #pragma unroll
        for (int o = 16; o; o >>= 1) mx = fmaxf(mx, __shfl_xor_sync(0xffffffffu, mx, o));
        float sum = 0.f;
        #pragma unroll
        for (int i = 0; i < 16; i++) { vals[i] = __expf(vals[i] - mx); sum += vals[i]; }
        #pragma unroll
        for (int o = 16; o; o >>= 1) sum += __shfl_xor_sync(0xffffffffu, sum, o);
        float inv = 1.0f / sum;
        #pragma unroll
        for (int k = 0; k < 8; k++)
            w8[k] = pack_bf(vals[k * 2] * inv, vals[k * 2 + 1] * inv);
        *(uint4*)&Ps[row * PSP + lane * 8]     = *(uint4*)&w8[0];
        *(uint4*)&Ps[row * PSP + lane * 8 + 4] = *(uint4*)&w8[4];
    }
    float acc[2][4][4];
    #pragma unroll
    for (int i = 0; i < 2; i++)
        #pragma unroll
        for (int j = 0; j < 4; j++)
            #pragma unroll
            for (int c = 0; c < 4; c++) acc[i][j][c] = 0.f;
    for (int k0 = 0; k0 < SEA; k0 += 32) {
        __syncthreads();
        #pragma unroll
        for (int u = 0; u < 4; u++) {
            int f = tid * 4 + u, row = f >> 3, q = f & 7;
            float4 v = *(const float4*)(mv + (size_t)row * SEA + k0 + q * 4);
            *(uint2*)&Bw[row * WP + q * 2] = make_uint2(pack_bf(v.x, v.y), pack_bf(v.z, v.w));
        }
        __syncthreads();
        #pragma unroll
        for (int ks = 0; ks < 2; ks++) {
            int kk = ks * 8;
            uint32_t a[2][4], b[4][2];
            #pragma unroll
            for (int mi = 0; mi < 2; mi++) {
                int mr = warpM * 32 + mi * 16;
                a[mi][0] = Ps[(mr + g) * PSP + (k0 >> 1) + kk + tg];
                a[mi][1] = Ps[(mr + g + 8) * PSP + (k0 >> 1) + kk + tg];
                a[mi][2] = Ps[(mr + g) * PSP + (k0 >> 1) + kk + tg + 4];
                a[mi][3] = Ps[(mr + g + 8) * PSP + (k0 >> 1) + kk + tg + 4];
            }
            #pragma unroll
            for (int ni = 0; ni < 4; ni++) {
                int nr = warpN * 32 + ni * 8 + g;
                b[ni][0] = Bw[nr * WP + kk + tg];
                b[ni][1] = Bw[nr * WP + kk + tg + 4];
            }
            #pragma unroll
            for (int mi = 0; mi < 2; mi++)
                #pragma unroll
                for (int ni = 0; ni < 4; ni++)
                    mma_bf16(acc[mi][ni], a[mi], b[ni]);
        }
    }
    __syncthreads();
    #pragma unroll
    for (int mi = 0; mi < 2; mi++)
        #pragma unroll
        for (int ni = 0; ni < 4; ni++) {
            int row = warpM * 32 + mi * 16 + g;
            int col = warpN * 32 + ni * 8 + tg * 2;
            *(float2*)&Cs[row * CSP + col]       = make_float2(acc[mi][ni][0], acc[mi][ni][1]);
            *(float2*)&Cs[(row + 8) * CSP + col] = make_float2(acc[mi][ni][2], acc[mi][ni][3]);
        }
    __syncthreads();
    for (int it = 0; it < 8; it++) {
        int r = wid * 8 + it;
        int gr = m0 + r;
        float vv[4], s = 0.f, q = 0.f;
        #pragma unroll
        for (int qq = 0; qq < 4; qq++) {
            vv[qq] = Cs[r * CSP + lane + qq * 32];
            s += vv[qq]; q += vv[qq] * vv[qq];
        }
        #pragma unroll
        for (int o = 16; o; o >>= 1) {
            s += __shfl_xor_sync(0xffffffffu, s, o);
            q += __shfl_xor_sync(0xffffffffu, q, o);
        }
        float mu = s * (1.0f / DM);
        float var = q * (1.0f / DM) - mu * mu;
        float istd = rsqrtf(var + EPS_F);
        #pragma unroll
        for (int qq = 0; qq < 4; qq++) {
            int d = lane + qq * 32;
            float ln = (vv[qq] - mu) * istd * lnw[d] + lnb[d];
            g_hb[(size_t)gr * DM + d] = gelu_exact(ln) + g_h[(size_t)gr * DM + d];
        }
    }
}

// ---------------- K3: in_proj + fused depthwise conv + SiLU ----------------
__global__ void __launch_bounds__(128) k_inproj(const float* __restrict__ W,
                        const float* __restrict__ cw, const float* __restrict__ cbv) {
    __shared__ uint32_t As[64][WP], Bs[64][WP];
    __shared__ float Cs[64][68];
    float acc[2][4][4];
    #pragma unroll
    for (int i = 0; i < 2; i++)
        #pragma unroll
        for (int j = 0; j < 4; j++)
            #pragma unroll
            for (int c = 0; c < 4; c++) acc[i][j][c] = 0.f;
    int m0 = blockIdx.x * 64, n0 = blockIdx.y * 64;
    gemm_bf16_64(g_hb, DM, W + (size_t)n0 * DM, DM, 64, m0, DM, 1 << 30, As, Bs, acc);
    int tid = threadIdx.x;
    int lane = tid & 31, wid = tid >> 5;
    int warpM = wid & 1, warpN = wid >> 1;
    int g = lane >> 2, tg = lane & 3;
    if (n0 >= 256) {
        int cb = n0 - 256;
        #pragma unroll
        for (int mi = 0; mi < 2; mi++)
            #pragma unroll
            for (int ni = 0; ni < 4; ni++) {
                int row = m0 + warpM * 32 + mi * 16 + g;
                int col = cb + warpN * 32 + ni * 8 + tg * 2;
                *(float2*)&g_z[(size_t)row * DIN + col] = make_float2(acc[mi][ni][0], acc[mi][ni][1]);
                *(float2*)&g_z[(size_t)(row + 8) * DIN + col] = make_float2(acc[mi][ni][2], acc[mi][ni][3]);
            }
        return;
    }
    #pragma unroll
    for (int mi = 0; mi < 2; mi++)
        #pragma unroll
        for (int ni = 0; ni < 4; ni++) {
            int row = warpM * 32 + mi * 16 + g;
            int col = warpN * 32 + ni * 8 + tg * 2;
            *(float2*)&Cs[row][col] = make_float2(acc[mi][ni][0], acc[mi][ni][1]);
            *(float2*)&Cs[row + 8][col] = make_float2(acc[mi][ni][2], acc[mi][ni][3]);
        }
    __syncthreads();
    int cb = n0;
    for (int idx = tid; idx < 64 * 64; idx += 128) {
        int l = idx >> 6, c = idx & 63;
        int gc = cb + c;
        float x0 = (l >= 3) ? Cs[l - 3][c] : 0.f;
        float x1 = (l >= 2) ? Cs[l - 2][c] : 0.f;
        float x2 = (l >= 1) ? Cs[l - 1][c] : 0.f;
        float x3 = Cs[l][c];
        const float4 wv = *(const float4*)(cw + gc * 4);
        float t = fmaf(x0, wv.x, fmaf(x1, wv.y, fmaf(x2, wv.z, fmaf(x3, wv.w, cbv[gc]))));
        g_xcc[(size_t)(m0 + l) * DIN + gc] = silu_f(t);
    }
}

// ---------------- K4: x_proj GEMM (21504 x 40 x 256) -> g_dbl ----------------
__global__ void __launch_bounds__(128) k_xprojg(const float* __restrict__ xpw) {
    __shared__ uint32_t As[64][WP], Bs[64][WP];
    float acc[2][4][4];
    #pragma unroll
    for (int i = 0; i < 2; i++)
        #pragma unroll
        for (int j = 0; j < 4; j++)
            #pragma unroll
            for (int c = 0; c < 4; c++) acc[i][j][c] = 0.f;
    int m0 = blockIdx.x * 64;
    gemm_bf16_64(g_xcc, DIN, xpw, DIN, 40, m0, DIN, 1 << 30, As, Bs, acc);
    int lane = threadIdx.x & 31, wid = threadIdx.x >> 5;
    int warpM = wid & 1, warpN = wid >> 1;
    int g = lane >> 2, tg = lane & 3;
    #pragma unroll
    for (int mi = 0; mi < 2; mi++)
        #pragma unroll
        for (int ni = 0; ni < 4; ni++) {
            int row = m0 + warpM * 32 + mi * 16 + g;
            int col = warpN * 32 + ni * 8 + tg * 2;
            if (col < 40) {
                *(float2*)&g_dbl[(size_t)row * 40 + col] = make_float2(acc[mi][ni][0], acc[mi][ni][1]);
                *(float2*)&g_dbl[(size_t)(row + 8) * 40 + col] = make_float2(acc[mi][ni][2], acc[mi][ni][3]);
            }
        }
}

// ---------------- K5: scan (+ fused dt_proj + softplus) ----------------
__global__ void k_scan(const float* __restrict__ A_log, const float* __restrict__ D_ssm,
                       const float* __restrict__ dtw, const float* __restrict__ dtb) {
    int bv = blockIdx.x, c = threadIdx.x;   // 256
    __shared__ float dbl[LSEQ][40];
    for (int i = c; i < LSEQ * 40; i += 256)
        dbl[i / 40][i % 40] = g_dbl[(size_t)bv * LSEQ * 40 + i];
    float dw[8];
    #pragma unroll
    for (int r = 0; r < 8; r++) dw[r] = dtw[c * 8 + r];
    float db = dtb[c];
    float As[DSS];
    #pragma unroll
    for (int s = 0; s < DSS; s++) As[s] = -expf(A_log[c * DSS + s]);
    float Dv = D_ssm[c];
    float st[DSS];
    #pragma unroll
    for (int s = 0; s < DSS; s++) st[s] = 0.f;
    __syncthreads();
    size_t base = (size_t)bv * LSEQ * DIN;
    for (int l = 0; l < LSEQ; l++) {
        float dt = db;
        #pragma unroll
        for (int r = 0; r < 8; r++) dt = fmaf(dbl[l][r], dw[r], dt);
        float d = (dt > 20.f) ? dt : log1pf(expf(dt));
        float u  = g_xcc[base + l * DIN + c];
        float zv = g_z  [base + l * DIN + c];
        float du = d * u;
        float y = 0.f;
        #pragma unroll
        for (int s = 0; s < DSS; s++) {
            float dA = __expf(d * As[s]);
            st[s] = fmaf(st[s], dA, du * dbl[l][8 + s]);
            y = fmaf(st[s], dbl[l][24 + s], y);
        }
        y = fmaf(Dv, u, y);
        y *= silu_f(zv);
        g_y[base + l * DIN + c] = y;
    }
}

// ---------------- K6: out_proj (21504x128x256) ----------------
__global__ void __launch_bounds__(128) k_outproj(const float* __restrict__ W) {
    __shared__ uint32_t As[64][WP], Bs[64][WP];
    float acc[2][4][4];
    #pragma unroll
    for (int i = 0; i < 2; i++)
        #pragma unroll
        for (int j = 0; j < 4; j++)
            #pragma unroll
            for (int c = 0; c < 4; c++) acc[i][j][c] = 0.f;
    int m0 = blockIdx.x * 64, n0 = blockIdx.y * 64;
    gemm_bf16_64(g_y, DIN, W + (size_t)n0 * DIN, DIN, 64, m0, DIN, 1 << 30, As, Bs, acc);
    int lane = threadIdx.x & 31, wid = threadIdx.x >> 5;
    int warpM = wid & 1, warpN = wid >> 1;
    int g = lane >> 2, tg = lane & 3;
    #pragma unroll
    for (int mi = 0; mi < 2; mi++)
        #pragma unroll
        for (int ni = 0; ni < 4; ni++) {
            int row = m0 + warpM * 32 + mi * 16 + g;
            int col = n0 + warpN * 32 + ni * 8 + tg * 2;
            *(float2*)&g_mo[(size_t)row * DM + col] = make_float2(acc[mi][ni][0], acc[mi][ni][1]);
            *(float2*)&g_mo[(size_t)(row + 8) * DM + col] = make_float2(acc[mi][ni][2], acc[mi][ni][3]);
        }
}

// ---------------- K7: mlp2 split-K partials (32 splits of K=256) -----------
__global__ void __launch_bounds__(128) k_mlp2p(const float* __restrict__ W) {
    __shared__ uint32_t As[64][WP], Bs[64][WP];
    float acc[2][4][4];
    #pragma unroll
    for (int i = 0; i < 2; i++)
        #pragma unroll
        for (int j = 0; j < 4; j++)
            #pragma unroll
            for (int c = 0; c < 4; c++) acc[i][j][c] = 0.f;
    int m0 = blockIdx.x * 64, n0 = blockIdx.y * 64, s = blockIdx.z;
    const float* A = g_mo + (size_t)s * 256;
    const float* B = W + (size_t)n0 * 8192 + (size_t)s * 256;
    gemm_bf16_64(A, 8192, B, 8192, 64, m0, 256, NBV, As, Bs, acc);
    int lane = threadIdx.x & 31, wid = threadIdx.x >> 5;
    int warpM = wid & 1, warpN = wid >> 1;
    int g = lane >> 2, tg = lane & 3;
    #pragma unroll
    for (int mi = 0; mi < 2; mi++)
        #pragma unroll
        for (int ni = 0; ni < 4; ni++) {
            int row = m0 + warpM * 32 + mi * 16 + g;
            int col = n0 + warpN * 32 + ni * 8 + tg * 2;
            if (row < NBV)
                *(float2*)&g_t2p[((size_t)s * NBV + row) * 192 + col] =
                    make_float2(acc[mi][ni][0], acc[mi][ni][1]);
            if (row + 8 < NBV)
                *(float2*)&g_t2p[((size_t)s * NBV + row + 8) * 192 + col] =
                    make_float2(acc[mi][ni][2], acc[mi][ni][3]);
        }
}

// ---------------- K8: reduce + GELU + mlp3 + denorm ----------------
__global__ void k_mlp2fin3(const float* __restrict__ bias2,
                           const float* __restrict__ W3, const float* __restrict__ b3,
                           const float* __restrict__ rw, const float* __restrict__ rb,
                           float* __restrict__ out) {
    int bv = blockIdx.x;
    int b = bv / NVAR, v = bv % NVAR;
    int tid = threadIdx.x;   // 192
    __shared__ float ts[192];
    float sum = 0.f;
    #pragma unroll
    for (int s = 0; s < NSPL; s++) sum += g_t2p[((size_t)s * NBV + bv) * 192 + tid];
    ts[tid] = gelu_exact(sum + bias2[tid]);
    __syncthreads();
    if (tid < PRED) {
        float acc = b3[tid];
        const float* w = W3 + tid * 192;
        #pragma unroll 4
        for (int j = 0; j < 192; j++) acc = fmaf(ts[j], w[j], acc);
        float val = (acc - rb[v]) / (rw[v] + 1e-10f) * g_std[bv] + g_mean[bv];
        out[((size_t)b * PRED + tid) * NVAR + v] = val;
    }
}

// ---------------- launch ----------------
extern "C" void kernel_launch(void* const* d_in, const int* in_sizes, int n_in,
                              void* d_out, int out_size) {
    const float* x         = (const float*)d_in[0];
    const float* revin_w   = (const float*)d_in[1];
    const float* revin_b   = (const float*)d_in[2];
    const float* mlp1_w    = (const float*)d_in[3];
    const float* mlp1_b    = (const float*)d_in[4];
    const float* mk_w      = (const float*)d_in[5];
    const float* mv_w      = (const float*)d_in[6];
    const float* ln_w      = (const float*)d_in[7];
    const float* ln_b      = (const float*)d_in[8];
    const float* in_proj_w = (const float*)d_in[9];
    const float* conv_w    = (const float*)d_in[10];
    const float* conv_b    = (const float*)d_in[11];
    const float* x_proj_w  = (const float*)d_in[12];
    const float* dt_proj_w = (const float*)d_in[13];
    const float* dt_proj_b = (const float*)d_in[14];
    const float* A_log     = (const float*)d_in[15];
    const float* D_ssm     = (const float*)d_in[16];
    const float* out_proj_w= (const float*)d_in[17];
    const float* mlp2_w    = (const float*)d_in[18];
    const float* mlp2_b    = (const float*)d_in[19];
    const float* mlp3_w    = (const float*)d_in[20];
    const float* mlp3_b    = (const float*)d_in[21];
    float* out = (float*)d_out;

    const int attn_smem = (64 * AHP + 64 * AHP + 64 * PSP) * 4;   // 101376 B
    cudaFuncSetAttribute(k_attn, cudaFuncAttributeMaxDynamicSharedMemorySize, attn_smem);

    k_revin_mlp1<<<NBV, 512>>>(x, revin_w, revin_b, mlp1_w, mlp1_b);
    k_attn    <<<NBV, 256, attn_smem>>>(mk_w, mv_w, ln_w, ln_b);
    k_inproj  <<<dim3(MROWS / 64, 8), 128>>>(in_proj_w, conv_w, conv_b);
    k_xprojg  <<<MROWS / 64, 128>>>(x_proj_w);
    k_scan    <<<NBV, 256>>>(A_log, D_ssm, dt_proj_w, dt_proj_b);
    k_outproj <<<dim3(MROWS / 64, 2), 128>>>(out_proj_w);
    k_mlp2p   <<<dim3(6, 3, NSPL), 128>>>(mlp2_w);
    k_mlp2fin3<<<NBV, 192>>>(mlp2_b, mlp3_w, mlp3_b, revin_w, revin_b, out);
}

// round 17
// speedup vs baseline: 1.8733x; 1.0212x over previous
#include <cuda_runtime.h>
#include <cuda_bf16.h>
#include <math.h>
#include <stdint.h>

#define NBV   336
#define NVAR  21
#define TT    512
#define TP    520
#define PNUM  64
#define DM    128
#define SEA   512
#define DIN   256
#define DSS   16
#define LSEQ  64
#define PRED  96
#define EPS_F 1e-5f
#define MROWS (NBV * PNUM)   // 21504
#define WP    20             // smem word pitch for k-chunk staging
#define AHP   68             // h/mk tile pitch (words)
#define PSP   260            // P tile pitch (words)
#define CSP   132            // C tile pitch (floats)
#define NSPL  32             // mlp2 split-K factor

// ---------------- scratch ----------------
__device__ float    g_mean[NBV];
__device__ float    g_std[NBV];
__device__ float    g_h  [MROWS * DM];
__device__ float    g_hb [MROWS * DM];
__device__ float    g_z   [MROWS * DIN];
__device__ float    g_xcc [MROWS * DIN];
__device__ float    g_dbl [MROWS * 40];
__device__ float    g_dbl2[MROWS * 40];
__device__ float    g_y   [MROWS * DIN];
__device__ float    g_mo  [MROWS * DM];
__device__ float    g_t2p [NSPL * NBV * 192];

__device__ __forceinline__ float gelu_exact(float x) {
    return 0.5f * x * (1.0f + erff(x * 0.70710678118654752f));
}
__device__ __forceinline__ float silu_f(float x) {
    return x / (1.0f + __expf(-x));
}
__device__ __forceinline__ uint32_t pack_bf(float a, float b) {
    __nv_bfloat162 t = __floats2bfloat162_rn(a, b);
    return *(uint32_t*)&t;
}
__device__ __forceinline__ void mma_bf16(float c[4], const uint32_t a[4], const uint32_t b[2]) {
    asm volatile("mma.sync.aligned.m16n8k16.row.col.f32.bf16.bf16.f32 "
        "{%0,%1,%2,%3},{%4,%5,%6,%7},{%8,%9},{%0,%1,%2,%3};"
        : "+f"(c[0]), "+f"(c[1]), "+f"(c[2]), "+f"(c[3])
        : "r"(a[0]), "r"(a[1]), "r"(a[2]), "r"(a[3]), "r"(b[0]), "r"(b[1]));
}

// ---------- bf16 64x64 tile core (NT), 128 threads, K-step 32 ----------
// Double-buffered via register prefetch: LDG for chunk k+1 issues before the
// mma block of chunk k, hiding the global-load latency behind compute.
__device__ __forceinline__ void gemm_bf16_64(
    const float* __restrict__ A, int lda,
    const float* __restrict__ Bn, int ldb, int Nvalid,
    int m0, int K, int Mmax,
    uint32_t As[64][WP], uint32_t Bs[64][WP],
    float acc[2][4][4])
{
    int tid = threadIdx.x;
    int lane = tid & 31, wid = tid >> 5;
    int warpM = wid & 1, warpN = wid >> 1;
    int g = lane >> 2, tg = lane & 3;
    int arow[4], aq[4];
    #pragma unroll
    for (int u = 0; u < 4; u++) {
        int f = tid * 4 + u;
        arow[u] = f >> 3; aq[u] = f & 7;
    }
    float4 va[4], vb[4];
    #pragma unroll
    for (int u = 0; u < 4; u++) {
        va[u] = make_float4(0.f, 0.f, 0.f, 0.f);
        int gr = m0 + arow[u];
        if (gr < Mmax) va[u] = *(const float4*)(A + (size_t)gr * lda + aq[u] * 4);
        vb[u] = make_float4(0.f, 0.f, 0.f, 0.f);
        if (arow[u] < Nvalid) vb[u] = *(const float4*)(Bn + (size_t)arow[u] * ldb + aq[u] * 4);
    }
    int nch = K >> 5;
    for (int ch = 0; ch < nch; ch++) {
        #pragma unroll
        for (int u = 0; u < 4; u++) {
            *(uint2*)&As[arow[u]][aq[u] * 2] =
                make_uint2(pack_bf(va[u].x, va[u].y), pack_bf(va[u].z, va[u].w));
            *(uint2*)&Bs[arow[u]][aq[u] * 2] =
                make_uint2(pack_bf(vb[u].x, vb[u].y), pack_bf(vb[u].z, vb[u].w));
        }
        __syncthreads();
        if (ch + 1 < nch) {
            int k0 = (ch + 1) * 32;
            #pragma unroll
            for (int u = 0; u < 4; u++) {
                va[u] = make_float4(0.f, 0.f, 0.f, 0.f);
                int gr = m0 + arow[u];
                if (gr < Mmax) va[u] = *(const float4*)(A + (size_t)gr * lda + k0 + aq[u] * 4);
                vb[u] = make_float4(0.f, 0.f, 0.f, 0.f);
                if (arow[u] < Nvalid) vb[u] = *(const float4*)(Bn + (size_t)arow[u] * ldb + k0 + aq[u] * 4);
            }
        }
        #pragma unroll
        for (int ks = 0; ks < 2; ks++) {
            int kk = ks * 8;
            uint32_t a[2][4], b[4][2];
            #pragma unroll
            for (int mi = 0; mi < 2; mi++) {
                int mr = warpM * 32 + mi * 16;
                a[mi][0] = As[mr + g][kk + tg];
                a[mi][1] = As[mr + g + 8][kk + tg];
                a[mi][2] = As[mr + g][kk + tg + 4];
                a[mi][3] = As[mr + g + 8][kk + tg + 4];
            }
            #pragma unroll
            for (int ni = 0; ni < 4; ni++) {
                int nr = warpN * 32 + ni * 8 + g;
                b[ni][0] = Bs[nr][kk + tg];
                b[ni][1] = Bs[nr][kk + tg + 4];
            }
            #pragma unroll
            for (int mi = 0; mi < 2; mi++)
                #pragma unroll
                for (int ni = 0; ni < 4; ni++)
                    mma_bf16(acc[mi][ni], a[mi], b[ni]);
        }
        __syncthreads();
    }
}

// ---------------- K1: RevIN + mlp1 fused ----------------
__global__ void __launch_bounds__(512) k_revin_mlp1(
        const float* __restrict__ x,
        const float* __restrict__ rw, const float* __restrict__ rb,
        const float* __restrict__ w1, const float* __restrict__ b1) {
    int bv = blockIdx.x;
    int b = bv / NVAR, v = bv % NVAR;
    int t = threadIdx.x;
    __shared__ float xs[TP];
    float val = x[(size_t)(b * TT + t) * NVAR + v];
    __shared__ float s1[16], s2[16];
    float a = val, q = val * val;
    #pragma unroll
    for (int o = 16; o; o >>= 1) {
        a += __shfl_down_sync(0xffffffffu, a, o);
        q += __shfl_down_sync(0xffffffffu, q, o);
    }
    if ((t & 31) == 0) { s1[t >> 5] = a; s2[t >> 5] = q; }
    __syncthreads();
    __shared__ float mb[2];
    if (t < 32) {
        float a2 = (t < 16) ? s1[t] : 0.f;
        float q2 = (t < 16) ? s2[t] : 0.f;
        #pragma unroll
        for (int o = 8; o; o >>= 1) {
            a2 += __shfl_down_sync(0xffffffffu, a2, o);
            q2 += __shfl_down_sync(0xffffffffu, q2, o);
        }
        if (t == 0) {
            float mean = a2 * (1.0f / TT);
            float var  = q2 * (1.0f / TT) - mean * mean;
            float sd   = sqrtf(var + EPS_F);
            mb[0] = mean; mb[1] = sd;
            g_mean[bv] = mean; g_std[bv] = sd;
        }
    }
    __syncthreads();
    float xnv = (val - mb[0]) / mb[1] * rw[v] + rb[v];
    xs[t] = xnv;
    if (t == TT - 1) {
        #pragma unroll
        for (int i = 0; i < 8; i++) xs[TT + i] = xnv;
    }
    __syncthreads();
    int d = t & 127, pg = t >> 7;
    float wr[16];
    #pragma unroll
    for (int s = 0; s < 16; s++) wr[s] = w1[d * 16 + s];
    float bb = b1[d];
    float* hp = g_h + (size_t)bv * PNUM * DM;
    #pragma unroll
    for (int pi = 0; pi < 16; pi++) {
        int p = pg * 16 + pi;
        float acc = bb;
        const float* xp = xs + p * 8;
        #pragma unroll
        for (int s = 0; s < 16; s++) acc = fmaf(xp[s], wr[s], acc);
        hp[p * DM + d] = acc;
    }
}

// ---------------- K2: fused attention, 101KB smem -> 2 CTA/SM ----------------
__global__ void __launch_bounds__(256, 2) k_attn(
        const float* __restrict__ mk, const float* __restrict__ mv,
        const float* __restrict__ lnw, const float* __restrict__ lnb) {
    extern __shared__ uint32_t smw[];
    uint32_t* Ah = smw;                       // [64][AHP]
    uint32_t* Bw = Ah + 64 * AHP;             // [64][AHP] scores-B / [128][WP] av-B
    uint32_t* Ps = Bw + 64 * AHP;             // [64][PSP]
    float*    Cs = (float*)Ps;                // aliases Ps, [64][CSP]
    int tid = threadIdx.x, lane = tid & 31, wid = tid >> 5;
    int warpM = wid & 1, warpN = wid >> 1;
    int g = lane >> 2, tg = lane & 3;
    int m0 = blockIdx.x * 64;

    #pragma unroll
    for (int u = 0; u < 8; u++) {
        int f = u * 256 + tid;
        int row = f >> 5, q = f & 31;
        float4 v = *(const float4*)(g_h + (size_t)(m0 + row) * DM + q * 4);
        Ah[row * AHP + q * 2]     = pack_bf(v.x, v.y);
        Ah[row * AHP + q * 2 + 1] = pack_bf(v.z, v.w);
    }
    for (int nc = 0; nc < 8; nc++) {
        __syncthreads();
        #pragma unroll
        for (int u = 0; u < 8; u++) {
            int f = u * 256 + tid;
            int row = f >> 5, q = f & 31;
            float4 v = *(const float4*)(mk + (size_t)(nc * 64 + row) * DM + q * 4);
            Bw[row * AHP + q * 2]     = pack_bf(v.x, v.y);
            Bw[row * AHP + q * 2 + 1] = pack_bf(v.z, v.w);
        }
        __syncthreads();
        float acc[2][2][4];
        #pragma unroll
        for (int i = 0; i < 2; i++)
            #pragma unroll
            for (int j = 0; j < 2; j++)
                #pragma unroll
                for (int c = 0; c < 4; c++) acc[i][j][c] = 0.f;
        #pragma unroll
        for (int ks = 0; ks < 8; ks++) {
            uint32_t a[2][4], b[2][2];
            #pragma unroll
            for (int mi = 0; mi < 2; mi++) {
                int mr = warpM * 32 + mi * 16;
                a[mi][0] = Ah[(mr + g) * AHP + ks * 8 + tg];
                a[mi][1] = Ah[(mr + g + 8) * AHP + ks * 8 + tg];
                a[mi][2] = Ah[(mr + g) * AHP + ks * 8 + tg + 4];
                a[mi][3] = Ah[(mr + g + 8) * AHP + ks * 8 + tg + 4];
            }
            #pragma unroll
            for (int ni = 0; ni < 2; ni++) {
                int nr = warpN * 16 + ni * 8 + g;
                b[ni][0] = Bw[nr * AHP + ks * 8 + tg];
                b[ni][1] = Bw[nr * AHP + ks * 8 + tg + 4];
            }
            #pragma unroll
            for (int mi = 0; mi < 2; mi++)
                #pragma unroll
                for (int ni = 0; ni < 2; ni++)
                    mma_bf16(acc[mi][ni], a[mi], b[ni]);
        }
        #pragma unroll
        for (int mi = 0; mi < 2; mi++)
            #pragma unroll
            for (int ni = 0; ni < 2; ni++) {
                int row = warpM * 32 + mi * 16 + g;
                int wcol = nc * 32 + warpN * 8 + ni * 4 + tg;
                Ps[row * PSP + wcol]       = pack_bf(acc[mi][ni][0], acc[mi][ni][1]);
                Ps[(row + 8) * PSP + wcol] = pack_bf(acc[mi][ni][2], acc[mi][ni][3]);
            }
    }
    __syncthreads();
    for (int rr = 0; rr < 8; rr++) {
        int row = wid * 8 + rr;
        uint32_t w8[8];
        *(uint4*)&w8[0] = *(uint4*)&Ps[row * PSP + lane * 8];
        *(uint4*)&w8[4] = *(uint4*)&Ps[row * PSP + lane * 8 + 4];
        float vals[16];
        #pragma unroll
        for (int k = 0; k < 8; k++) {
            float2 f = __bfloat1622float2(*(__nv_bfloat162*)&w8[k]);
            vals[k * 2] = f.x; vals[k * 2 + 1] = f.y;
        }
        float mx = -1e30f;
        #pragma unroll
        for (int i = 0; i < 16; i++) mx = fmaxf(mx, vals[i]);
        #pragma unroll
        for (int o = 16; o; o >>= 1) mx = fmaxf(mx, __shfl_xor_sync(0xffffffffu, mx, o));
        float sum = 0.f;
        #pragma unroll
        for (int i = 0; i < 16; i++) { vals[i] = __expf(vals[i] - mx); sum += vals[i]; }
        #pragma unroll
        for (int o = 16; o; o >>= 1) sum += __shfl_xor_sync(0xffffffffu, sum, o);
        float inv = 1.0f / sum;
        #pragma unroll
        for (int k = 0; k < 8; k++)
            w8[k] = pack_bf(vals[k * 2] * inv, vals[k * 2 + 1] * inv);
        *(uint4*)&Ps[row * PSP + lane * 8]     = *(uint4*)&w8[0];
        *(uint4*)&Ps[row * PSP + lane * 8 + 4] = *(uint4*)&w8[4];
    }
    // ---- AV: P(64x512) @ mv^T(128x512), mv prefetched in registers ----
    float acc[2][4][4];
    #pragma unroll
    for (int i = 0; i < 2; i++)
        #pragma unroll
        for (int j = 0; j < 4; j++)
            #pragma unroll
            for (int c = 0; c < 4; c++) acc[i][j][c] = 0.f;
    float4 vpf[4];
    #pragma unroll
    for (int u = 0; u < 4; u++) {
        int f = tid * 4 + u, row = f >> 3, q = f & 7;
        vpf[u] = *(const float4*)(mv + (size_t)row * SEA + q * 4);
    }
    for (int k0 = 0; k0 < SEA; k0 += 32) {
        __syncthreads();
        #pragma unroll
        for (int u = 0; u < 4; u++) {
            int f = tid * 4 + u, row = f >> 3, q = f & 7;
            *(uint2*)&Bw[row * WP + q * 2] =
                make_uint2(pack_bf(vpf[u].x, vpf[u].y), pack_bf(vpf[u].z, vpf[u].w));
        }
        __syncthreads();
        if (k0 + 32 < SEA) {
            #pragma unroll
            for (int u = 0; u < 4; u++) {
                int f = tid * 4 + u, row = f >> 3, q = f & 7;
                vpf[u] = *(const float4*)(mv + (size_t)row * SEA + k0 + 32 + q * 4);
            }
        }
        #pragma unroll
        for (int ks = 0; ks < 2; ks++) {
            int kk = ks * 8;
            uint32_t a[2][4], b[4][2];
            #pragma unroll
            for (int mi = 0; mi < 2; mi++) {
                int mr = warpM * 32 + mi * 16;
                a[mi][0] = Ps[(mr + g) * PSP + (k0 >> 1) + kk + tg];
                a[mi][1] = Ps[(mr + g + 8) * PSP + (k0 >> 1) + kk + tg];
                a[mi][2] = Ps[(mr + g) * PSP + (k0 >> 1) + kk + tg + 4];
                a[mi][3] = Ps[(mr + g + 8) * PSP + (k0 >> 1) + kk + tg + 4];
            }
            #pragma unroll
            for (int ni = 0; ni < 4; ni++) {
                int nr = warpN * 32 + ni * 8 + g;
                b[ni][0] = Bw[nr * WP + kk + tg];
                b[ni][1] = Bw[nr * WP + kk + tg + 4];
            }
            #pragma unroll
            for (int mi = 0; mi < 2; mi++)
                #pragma unroll
                for (int ni = 0; ni < 4; ni++)
                    mma_bf16(acc[mi][ni], a[mi], b[ni]);
        }
    }
    __syncthreads();
    #pragma unroll
    for (int mi = 0; mi < 2; mi++)
        #pragma unroll
        for (int ni = 0; ni < 4; ni++) {
            int row = warpM * 32 + mi * 16 + g;
            int col = warpN * 32 + ni * 8 + tg * 2;
            *(float2*)&Cs[row * CSP + col]       = make_float2(acc[mi][ni][0], acc[mi][ni][1]);
            *(float2*)&Cs[(row + 8) * CSP + col] = make_float2(acc[mi][ni][2], acc[mi][ni][3]);
        }
    __syncthreads();
    for (int it = 0; it < 8; it++) {
        int r = wid * 8 + it;
        int gr = m0 + r;
        float vv[4], s = 0.f, q = 0.f;
        #pragma unroll
        for (int qq = 0; qq < 4; qq++) {
            vv[qq] = Cs[r * CSP + lane + qq * 32];
            s += vv[qq]; q += vv[qq] * vv[qq];
        }
        #pragma unroll
        for (int o = 16; o; o >>= 1) {
            s += __shfl_xor_sync(0xffffffffu, s, o);
            q += __shfl_xor_sync(0xffffffffu, q, o);
        }
        float mu = s * (1.0f / DM);
        float var = q * (1.0f / DM) - mu * mu;
        float istd = rsqrtf(var + EPS_F);
        #pragma unroll
        for (int qq = 0; qq < 4; qq++) {
            int d = lane + qq * 32;
            float ln = (vv[qq] - mu) * istd * lnw[d] + lnb[d];
            g_hb[(size_t)gr * DM + d] = gelu_exact(ln) + g_h[(size_t)gr * DM + d];
        }
    }
}

// ---------------- K3: in_proj + fused depthwise conv + SiLU ----------------
__global__ void __launch_bounds__(128) k_inproj(const float* __restrict__ W,
                        const float* __restrict__ cw, const float* __restrict__ cbv) {
    __shared__ uint32_t As[64][WP], Bs[64][WP];
    __shared__ float Cs[64][68];
    float acc[2][4][4];
    #pragma unroll
    for (int i = 0; i < 2; i++)
        #pragma unroll
        for (int j = 0; j < 4; j++)
            #pragma unroll
            for (int c = 0; c < 4; c++) acc[i][j][c] = 0.f;
    int m0 = blockIdx.x * 64, n0 = blockIdx.y * 64;
    gemm_bf16_64(g_hb, DM, W + (size_t)n0 * DM, DM, 64, m0, DM, 1 << 30, As, Bs, acc);
    int tid = threadIdx.x;
    int lane = tid & 31, wid = tid >> 5;
    int warpM = wid & 1, warpN = wid >> 1;
    int g = lane >> 2, tg = lane & 3;
    if (n0 >= 256) {
        int cb = n0 - 256;
        #pragma unroll
        for (int mi = 0; mi < 2; mi++)
            #pragma unroll
            for (int ni = 0; ni < 4; ni++) {
                int row = m0 + warpM * 32 + mi * 16 + g;
                int col = cb + warpN * 32 + ni * 8 + tg * 2;
                *(float2*)&g_z[(size_t)row * DIN + col] = make_float2(acc[mi][ni][0], acc[mi][ni][1]);
                *(float2*)&g_z[(size_t)(row + 8) * DIN + col] = make_float2(acc[mi][ni][2], acc[mi][ni][3]);
            }
        return;
    }
    #pragma unroll
    for (int mi = 0; mi < 2; mi++)
        #pragma unroll
        for (int ni = 0; ni < 4; ni++) {
            int row = warpM * 32 + mi * 16 + g;
            int col = warpN * 32 + ni * 8 + tg * 2;
            *(float2*)&Cs[row][col] = make_float2(acc[mi][ni][0], acc[mi][ni][1]);
            *(float2*)&Cs[row + 8][col] = make_float2(acc[mi][ni][2], acc[mi][ni][3]);
        }
    __syncthreads();
    int cb = n0;
    for (int idx = tid; idx < 64 * 64; idx += 128) {
        int l = idx >> 6, c = idx & 63;
        int gc = cb + c;
        float x0 = (l >= 3) ? Cs[l - 3][c] : 0.f;
        float x1 = (l >= 2) ? Cs[l - 2][c] : 0.f;
        float x2 = (l >= 1) ? Cs[l - 1][c] : 0.f;
        float x3 = Cs[l][c];
        const float4 wv = *(const float4*)(cw + gc * 4);
        float t = fmaf(x0, wv.x, fmaf(x1, wv.y, fmaf(x2, wv.z, fmaf(x3, wv.w, cbv[gc]))));
        g_xcc[(size_t)(m0 + l) * DIN + gc] = silu_f(t);
    }
}

// ---------------- K4: x_proj GEMM split-K=2 (21504 x 40 x 128 each) ----------
__global__ void __launch_bounds__(128) k_xprojg(const float* __restrict__ xpw) {
    __shared__ uint32_t As[64][WP], Bs[64][WP];
    float acc[2][4][4];
    #pragma unroll
    for (int i = 0; i < 2; i++)
        #pragma unroll
        for (int j = 0; j < 4; j++)
            #pragma unroll
            for (int c = 0; c < 4; c++) acc[i][j][c] = 0.f;
    int m0 = blockIdx.x * 64, s = blockIdx.y;
    gemm_bf16_64(g_xcc + s * 128, DIN, xpw + s * 128, DIN, 40, m0, 128, 1 << 30, As, Bs, acc);
    float* dst = s ? g_dbl2 : g_dbl;
    int lane = threadIdx.x & 31, wid = threadIdx.x >> 5;
    int warpM = wid & 1, warpN = wid >> 1;
    int g = lane >> 2, tg = lane & 3;
    #pragma unroll
    for (int mi = 0; mi < 2; mi++)
        #pragma unroll
        for (int ni = 0; ni < 4; ni++) {
            int row = m0 + warpM * 32 + mi * 16 + g;
            int col = warpN * 32 + ni * 8 + tg * 2;
            if (col < 40) {
                *(float2*)&dst[(size_t)row * 40 + col] = make_float2(acc[mi][ni][0], acc[mi][ni][1]);
                *(float2*)&dst[(size_t)(row + 8) * 40 + col] = make_float2(acc[mi][ni][2], acc[mi][ni][3]);
            }
        }
}

// ---------------- K5: scan (+ fused dt_proj + softplus, sums split-K) -------
__global__ void k_scan(const float* __restrict__ A_log, const float* __restrict__ D_ssm,
                       const float* __restrict__ dtw, const float* __restrict__ dtb) {
    int bv = blockIdx.x, c = threadIdx.x;   // 256
    __shared__ float dbl[LSEQ][40];
    for (int i = c; i < LSEQ * 40; i += 256)
        dbl[i / 40][i % 40] = g_dbl[(size_t)bv * LSEQ * 40 + i] + g_dbl2[(size_t)bv * LSEQ * 40 + i];
    float dw[8];
    #pragma unroll
    for (int r = 0; r < 8; r++) dw[r] = dtw[c * 8 + r];
    float db = dtb[c];
    float As[DSS];
    #pragma unroll
    for (int s = 0; s < DSS; s++) As[s] = -expf(A_log[c * DSS + s]);
    float Dv = D_ssm[c];
    float st[DSS];
    #pragma unroll
    for (int s = 0; s < DSS; s++) st[s] = 0.f;
    __syncthreads();
    size_t base = (size_t)bv * LSEQ * DIN;
    for (int l = 0; l < LSEQ; l++) {
        float dt = db;
        #pragma unroll
        for (int r = 0; r < 8; r++) dt = fmaf(dbl[l][r], dw[r], dt);
        float d = (dt > 20.f) ? dt : log1pf(expf(dt));
        float u  = g_xcc[base + l * DIN + c];
        float zv = g_z  [base + l * DIN + c];
        float du = d * u;
        float y = 0.f;
        #pragma unroll
        for (int s = 0; s < DSS; s++) {
            float dA = __expf(d * As[s]);
            st[s] = fmaf(st[s], dA, du * dbl[l][8 + s]);
            y = fmaf(st[s], dbl[l][24 + s], y);
        }
        y = fmaf(Dv, u, y);
        y *= silu_f(zv);
        g_y[base + l * DIN + c] = y;
    }
}

// ---------------- K6: out_proj (21504x128x256) ----------------
__global__ void __launch_bounds__(128) k_outproj(const float* __restrict__ W) {
    __shared__ uint32_t As[64][WP], Bs[64][WP];
    float acc[2][4][4];
    #pragma unroll
    for (int i = 0; i < 2; i++)
        #pragma unroll
        for (int j = 0; j < 4; j++)
            #pragma unroll
            for (int c = 0; c < 4; c++) acc[i][j][c] = 0.f;
    int m0 = blockIdx.x * 64, n0 = blockIdx.y * 64;
    gemm_bf16_64(g_y, DIN, W + (size_t)n0 * DIN, DIN, 64, m0, DIN, 1 << 30, As, Bs, acc);
    int lane = threadIdx.x & 31, wid = threadIdx.x >> 5;
    int warpM = wid & 1, warpN = wid >> 1;
    int g = lane >> 2, tg = lane & 3;
    #pragma unroll
    for (int mi = 0; mi < 2; mi++)
        #pragma unroll
        for (int ni = 0; ni < 4; ni++) {
            int row = m0 + warpM * 32 + mi * 16 + g;
            int col = n0 + warpN * 32 + ni * 8 + tg * 2;
            *(float2*)&g_mo[(size_t)row * DM + col] = make_float2(acc[mi][ni][0], acc[mi][ni][1]);
            *(float2*)&g_mo[(size_t)(row + 8) * DM + col] = make_float2(acc[mi][ni][2], acc[mi][ni][3]);
        }
}

// ---------------- K7: mlp2 split-K partials (32 splits of K=256) -----------
__global__ void __launch_bounds__(128) k_mlp2p(const float* __restrict__ W) {
    __shared__ uint32_t As[64][WP], Bs[64][WP];
    float acc[2][4][4];
    #pragma unroll
    for (int i = 0; i < 2; i++)
        #pragma unroll
        for (int j = 0; j < 4; j++)
            #pragma unroll
            for (int c = 0; c < 4; c++) acc[i][j][c] = 0.f;
    int m0 = blockIdx.x * 64, n0 = blockIdx.y * 64, s = blockIdx.z;
    const float* A = g_mo + (size_t)s * 256;
    const float* B = W + (size_t)n0 * 8192 + (size_t)s * 256;
    gemm_bf16_64(A, 8192, B, 8192, 64, m0, 256, NBV, As, Bs, acc);
    int lane = threadIdx.x & 31, wid = threadIdx.x >> 5;
    int warpM = wid & 1, warpN = wid >> 1;
    int g = lane >> 2, tg = lane & 3;
    #pragma unroll
    for (int mi = 0; mi < 2; mi++)
        #pragma unroll
        for (int ni = 0; ni < 4; ni++) {
            int row = m0 + warpM * 32 + mi * 16 + g;
            int col = n0 + warpN * 32 + ni * 8 + tg * 2;
            if (row < NBV)
                *(float2*)&g_t2p[((size_t)s * NBV + row) * 192 + col] =
                    make_float2(acc[mi][ni][0], acc[mi][ni][1]);
            if (row + 8 < NBV)
                *(float2*)&g_t2p[((size_t)s * NBV + row + 8) * 192 + col] =
                    make_float2(acc[mi][ni][2], acc[mi][ni][3]);
        }
}

// ---------------- K8: reduce + GELU + mlp3 + denorm ----------------
__global__ void k_mlp2fin3(const float* __restrict__ bias2,
                           const float* __restrict__ W3, const float* __restrict__ b3,
                           const float* __restrict__ rw, const float* __restrict__ rb,
                           float* __restrict__ out) {
    int bv = blockIdx.x;
    int b = bv / NVAR, v = bv % NVAR;
    int tid = threadIdx.x;   // 192
    __shared__ float ts[192];
    float sum = 0.f;
    #pragma unroll
    for (int s = 0; s < NSPL; s++) sum += g_t2p[((size_t)s * NBV + bv) * 192 + tid];
    ts[tid] = gelu_exact(sum + bias2[tid]);
    __syncthreads();
    if (tid < PRED) {
        float acc = b3[tid];
        const float* w = W3 + tid * 192;
        #pragma unroll 4
        for (int j = 0; j < 192; j++) acc = fmaf(ts[j], w[j], acc);
        float val = (acc - rb[v]) / (rw[v] + 1e-10f) * g_std[bv] + g_mean[bv];
        out[((size_t)b * PRED + tid) * NVAR + v] = val;
    }
}

// ---------------- launch ----------------
extern "C" void kernel_launch(void* const* d_in, const int* in_sizes, int n_in,
                              void* d_out, int out_size) {
    const float* x         = (const float*)d_in[0];
    const float* revin_w   = (const float*)d_in[1];
    const float* revin_b   = (const float*)d_in[2];
    const float* mlp1_w    = (const float*)d_in[3];
    const float* mlp1_b    = (const float*)d_in[4];
    const float* mk_w      = (const float*)d_in[5];
    const float* mv_w      = (const float*)d_in[6];
    const float* ln_w      = (const float*)d_in[7];
    const float* ln_b      = (const float*)d_in[8];
    const float* in_proj_w = (const float*)d_in[9];
    const float* conv_w    = (const float*)d_in[10];
    const float* conv_b    = (const float*)d_in[11];
    const float* x_proj_w  = (const float*)d_in[12];
    const float* dt_proj_w = (const float*)d_in[13];
    const float* dt_proj_b = (const float*)d_in[14];
    const float* A_log     = (const float*)d_in[15];
    const float* D_ssm     = (const float*)d_in[16];
    const float* out_proj_w= (const float*)d_in[17];
    const float* mlp2_w    = (const float*)d_in[18];
    const float* mlp2_b    = (const float*)d_in[19];
    const float* mlp3_w    = (const float*)d_in[20];
    const float* mlp3_b    = (const float*)d_in[21];
    float* out = (float*)d_out;

    const int attn_smem = (64 * AHP + 64 * AHP + 64 * PSP) * 4;   // 101376 B
    cudaFuncSetAttribute(k_attn, cudaFuncAttributeMaxDynamicSharedMemorySize, attn_smem);

    k_revin_mlp1<<<NBV, 512>>>(x, revin_w, revin_b, mlp1_w, mlp1_b);
    k_attn    <<<NBV, 256, attn_smem>>>(mk_w, mv_w, ln_w, ln_b);
    k_inproj  <<<dim3(MROWS / 64, 8), 128>>>(in_proj_w, conv_w, conv_b);
    k_xprojg  <<<dim3(MROWS / 64, 2), 128>>>(x_proj_w);
    k_scan    <<<NBV, 256>>>(A_log, D_ssm, dt_proj_w, dt_proj_b);
    k_outproj <<<dim3(MROWS / 64, 2), 128>>>(out_proj_w);
    k_mlp2p   <<<dim3(6, 3, NSPL), 128>>>(mlp2_w);
    k_mlp2fin3<<<NBV, 192>>>(mlp2_b, mlp3_w, mlp3_b, revin_w, revin_b, out);
}